// round 8
// baseline (speedup 1.0000x reference)
#include <cuda_runtime.h>
#include <cstdint>

#define FULLM 0xFFFFFFFFu
#define BIGF  3.402823466e+38f

__device__ float g_feat[256*1024*16]; // stage-1 per-point features (B,N,16)
__device__ float g_fs[256*512*8];     // squeezed features on xyz1 (B,512,8)
__device__ float g_psum[256*2*128];   // per-block partial sums of f2 (B,2,128)

__device__ __forceinline__ float lrelu(float x){ return x > 0.f ? x : 0.2f*x; }

// ---- packed f32x2 helpers (Blackwell) -------------------------------------
__device__ __forceinline__ unsigned long long pk(float lo, float hi){
    unsigned long long r;
    asm("mov.b64 %0, {%1, %2};" : "=l"(r) : "f"(lo), "f"(hi));
    return r;
}
__device__ __forceinline__ float2 upk(unsigned long long v){
    float2 r;
    asm("mov.b64 {%0, %1}, %2;" : "=f"(r.x), "=f"(r.y) : "l"(v));
    return r;
}
__device__ __forceinline__ unsigned long long ffma2(
    unsigned long long a, unsigned long long b, unsigned long long c){
    unsigned long long d;
    asm("fma.rn.f32x2 %0, %1, %2, %3;" : "=l"(d) : "l"(a), "l"(b), "l"(c));
    return d;
}

__device__ __forceinline__ float qdist(const float4& v, float qx, float qy, float qz){
    // d' = |p|^2 - 2 q.p  (query-constant |q|^2 dropped: order-preserving)
    return fmaf(-2.f, fmaf(qx, v.x, fmaf(qy, v.y, qz*v.z)), v.w);
}

// Value-only bitonic sort of 32 floats across a warp (ascending).
__device__ __forceinline__ float bsort32_val(float s, int lane){
    #pragma unroll
    for (int k = 2; k <= 32; k <<= 1){
        #pragma unroll
        for (int j = k >> 1; j > 0; j >>= 1){
            float o = __shfl_xor_sync(FULLM, s, j);
            bool keepmin = ((lane & j) == 0) == ((lane & k) == 0);
            s = keepmin ? fminf(s, o) : fmaxf(s, o);
        }
    }
    return s;
}

// Dual value-only bitonic sort: two independent chains interleaved so the
// SHFL latency of one hides the ALU of the other.
__device__ __forceinline__ void bsort32_val2(float& a, float& b, int lane){
    #pragma unroll
    for (int k = 2; k <= 32; k <<= 1){
        #pragma unroll
        for (int j = k >> 1; j > 0; j >>= 1){
            float oa = __shfl_xor_sync(FULLM, a, j);
            float ob = __shfl_xor_sync(FULLM, b, j);
            bool keepmin = ((lane & j) == 0) == ((lane & k) == 0);
            a = keepmin ? fminf(a, oa) : fmaxf(a, oa);
            b = keepmin ? fminf(b, ob) : fmaxf(b, ob);
        }
    }
}

// Bitonic sort of 32 (d,i) pairs across a warp, ascending lex (d, then i).
__device__ __forceinline__ void bsort32_pair(float& d, int& i, int lane){
    #pragma unroll
    for (int k = 2; k <= 32; k <<= 1){
        #pragma unroll
        for (int j = k >> 1; j > 0; j >>= 1){
            float od = __shfl_xor_sync(FULLM, d, j);
            int   oi = __shfl_xor_sync(FULLM, i, j);
            bool lower = (lane & j) == 0;
            bool asc   = (lane & k) == 0;
            bool osm   = (od < d) || (od == d && oi < i);
            bool take  = (lower == asc) ? osm : !osm;
            if (take){ d = od; i = oi; }
        }
    }
}

// Single-query phase-4: exact top-16 set from a <=32-entry (d,idx) buffer.
__device__ __forceinline__ int resolve16(unsigned long long* spair, int lane, unsigned lt){
    float2 du = upk(spair[lane]);
    float d2 = du.x; int i2 = __float_as_int(du.y);
    float thr16 = __shfl_sync(FULLM, bsort32_val(d2, lane), 15);
    unsigned sel = __ballot_sync(FULLM, d2 <= thr16);
    if (__popc(sel) == 16){
        __syncwarp();
        int* ib = reinterpret_cast<int*>(spair);
        if (d2 <= thr16) ib[__popc(sel & lt)] = i2;
        __syncwarp();
        return ib[lane & 15];
    }
    bsort32_pair(d2, i2, lane);
    return i2;
}

// Rare fallback: progressive argmin with lex exclusion (exact).
template<int NT>
__device__ __forceinline__ int fallback16(const float4* __restrict__ sp,
                                          float4 q, int lane){
    float lastD = -BIGF; int lastI = -1; int kidx = 0x7FFFFFFF;
    for (int r = 0; r < 16; r++){
        float cbd = BIGF; int cbi = 0x7FFFFFFF;
        #pragma unroll
        for (int t = 0; t < NT; t++){
            int j = lane + t*32;
            float d = qdist(sp[j], q.x, q.y, q.z);
            bool gt = (d > lastD) || (d == lastD && j > lastI);
            if (gt && ((d < cbd) || (d == cbd && j < cbi))){ cbd = d; cbi = j; }
        }
        #pragma unroll
        for (int off = 16; off > 0; off >>= 1){
            float od = __shfl_down_sync(FULLM, cbd, off);
            int   oi = __shfl_down_sync(FULLM, cbi, off);
            if (od < cbd || (od == cbd && oi < cbi)){ cbd = od; cbi = oi; }
        }
        lastD = __shfl_sync(FULLM, cbd, 0);
        lastI = __shfl_sync(FULLM, cbi, 0);
        if (lane == r) kidx = lastI;
    }
    return kidx;
}

// Dual-query exact top-16 over NT*32 candidates. Shares candidate loads and
// interleaves both queries' bitonic chains. Results: lane-distributed sets
// (lanes 0..15 hold the 16 indices; order arbitrary — callers max-pool).
template<int NT>
__device__ __forceinline__ void knn16_dual(
    const float4* __restrict__ sp, float4 qa, float4 qb, int lane,
    unsigned long long* __restrict__ spA, unsigned long long* __restrict__ spB,
    int& kidxA, int& kidxB)
{
    // --- phase 1: shared loads, per-lane min for both queries ---------------
    float a0 = BIGF, a1 = BIGF, b0 = BIGF, b1 = BIGF;
    #pragma unroll
    for (int t = 0; t < NT; t += 2){
        float4 v0 = sp[lane + (t  )*32];
        float4 v1 = sp[lane + (t+1)*32];
        a0 = fminf(a0, qdist(v0, qa.x, qa.y, qa.z));
        b0 = fminf(b0, qdist(v0, qb.x, qb.y, qb.z));
        a1 = fminf(a1, qdist(v1, qa.x, qa.y, qa.z));
        b1 = fminf(b1, qdist(v1, qb.x, qb.y, qb.z));
    }
    float sA = fminf(a0, a1), sB = fminf(b0, b1);

    // --- phase 2: dual bitonic -> 16th-smallest lane-min thresholds --------
    bsort32_val2(sA, sB, lane);
    float thrA = __shfl_sync(FULLM, sA, 15);
    float thrB = __shfl_sync(FULLM, sB, 15);

    // --- phase 3: shared loads, dual ballot-compaction ----------------------
    spA[lane] = pk(BIGF, __int_as_float(0x7FFFFFFF));
    spB[lane] = pk(BIGF, __int_as_float(0x7FFFFFFF));
    __syncwarp();
    unsigned lt = (1u << lane) - 1u;
    int cntA = 0, cntB = 0;
    #pragma unroll
    for (int t = 0; t < NT; t++){
        float4 v = sp[lane + t*32];
        float dA = qdist(v, qa.x, qa.y, qa.z);
        float dB = qdist(v, qb.x, qb.y, qb.z);
        bool pA = (dA <= thrA), pB = (dB <= thrB);
        unsigned mA = __ballot_sync(FULLM, pA);
        unsigned mB = __ballot_sync(FULLM, pB);
        if (pA){ int pos = cntA + __popc(mA & lt);
                 if (pos < 32) spA[pos] = pk(dA, __int_as_float(lane + t*32)); }
        if (pB){ int pos = cntB + __popc(mB & lt);
                 if (pos < 32) spB[pos] = pk(dB, __int_as_float(lane + t*32)); }
        cntA += __popc(mA); cntB += __popc(mB);
    }
    __syncwarp();

    // --- phase 4: dual fast path, per-query slow paths ----------------------
    if (cntA <= 32 && cntB <= 32){
        float2 duA = upk(spA[lane]); float dA2 = duA.x; int iA2 = __float_as_int(duA.y);
        float2 duB = upk(spB[lane]); float dB2 = duB.x; int iB2 = __float_as_int(duB.y);
        float tA = dA2, tB = dB2;
        bsort32_val2(tA, tB, lane);
        float t16A = __shfl_sync(FULLM, tA, 15);
        float t16B = __shfl_sync(FULLM, tB, 15);
        unsigned selA = __ballot_sync(FULLM, dA2 <= t16A);
        unsigned selB = __ballot_sync(FULLM, dB2 <= t16B);
        bool okA = (__popc(selA) == 16), okB = (__popc(selB) == 16);
        __syncwarp();
        int* ibA = reinterpret_cast<int*>(spA);
        int* ibB = reinterpret_cast<int*>(spB);
        if (okA && dA2 <= t16A) ibA[__popc(selA & lt)] = iA2;
        if (okB && dB2 <= t16B) ibB[__popc(selB & lt)] = iB2;
        __syncwarp();
        if (okA) kidxA = ibA[lane & 15];
        else { float dd = dA2; int ii = iA2; bsort32_pair(dd, ii, lane); kidxA = ii; }
        if (okB) kidxB = ibB[lane & 15];
        else { float dd = dB2; int ii = iB2; bsort32_pair(dd, ii, lane); kidxB = ii; }
    } else {
        kidxA = (cntA <= 32) ? resolve16(spA, lane, lt) : fallback16<NT>(sp, qa, lane);
        kidxB = (cntB <= 32) ? resolve16(spB, lane, lt) : fallback16<NT>(sp, qb, lane);
    }
}

// ---------------------------------------------------------------------------
// Kernel A: f = lrelu(LN(lrelu(LN(xyz@W0+b0))@W1+b1))  per point
// ---------------------------------------------------------------------------
__global__ void __launch_bounds__(256) kA(
    const float* __restrict__ pc,
    const float* __restrict__ W0, const float* __restrict__ b0,
    const float* __restrict__ g0, const float* __restrict__ be0,
    const float* __restrict__ W1, const float* __restrict__ b1,
    const float* __restrict__ g1, const float* __restrict__ be1)
{
    int i = blockIdx.x*256 + threadIdx.x;
    int b = i >> 10, n = i & 1023;
    const float* p = pc + (size_t)b*3072;
    float x = p[n], y = p[1024+n], z = p[2048+n];

    float t[16];
    #pragma unroll
    for (int c=0;c<16;c++)
        t[c] = fmaf(x, __ldg(&W0[c]), fmaf(y, __ldg(&W0[16+c]), fmaf(z, __ldg(&W0[32+c]), __ldg(&b0[c]))));
    {
        float m=0.f;
        #pragma unroll
        for (int c=0;c<16;c++) m += t[c];
        m *= (1.f/16.f);
        float v=0.f;
        #pragma unroll
        for (int c=0;c<16;c++){ float dd=t[c]-m; v = fmaf(dd,dd,v); }
        v *= (1.f/16.f);
        float inv = rsqrtf(v + 1e-5f);
        #pragma unroll
        for (int c=0;c<16;c++)
            t[c] = lrelu(fmaf((t[c]-m)*inv, __ldg(&g0[c]), __ldg(&be0[c])));
    }
    float u[16];
    #pragma unroll
    for (int o=0;o<16;o++){
        float a = __ldg(&b1[o]);
        #pragma unroll
        for (int c=0;c<16;c++) a = fmaf(t[c], __ldg(&W1[c*16+o]), a);
        u[o] = a;
    }
    {
        float m=0.f;
        #pragma unroll
        for (int c=0;c<16;c++) m += u[c];
        m *= (1.f/16.f);
        float v=0.f;
        #pragma unroll
        for (int c=0;c<16;c++){ float dd=u[c]-m; v = fmaf(dd,dd,v); }
        v *= (1.f/16.f);
        float inv = rsqrtf(v + 1e-5f);
        #pragma unroll
        for (int c=0;c<16;c++)
            u[c] = lrelu(fmaf((u[c]-m)*inv, __ldg(&g1[c]), __ldg(&be1[c])));
    }
    float4* o4 = reinterpret_cast<float4*>(g_feat + (size_t)i*16);
    o4[0] = make_float4(u[0],u[1],u[2],u[3]);
    o4[1] = make_float4(u[4],u[5],u[6],u[7]);
    o4[2] = make_float4(u[8],u[9],u[10],u[11]);
    o4[3] = make_float4(u[12],u[13],u[14],u[15]);
}

// ---------------------------------------------------------------------------
// kB per-query tail: gather + GEMM + fused squeeze
// ---------------------------------------------------------------------------
__device__ __forceinline__ void kb_tail(
    int b, int m, float4 q, int kidx, int lane, int jq, int cb,
    const float4* __restrict__ sp4, float* __restrict__ sgw,
    float* __restrict__ smx,
    const unsigned long long* __restrict__ wp, float wr18,
    unsigned long long accp,
    const unsigned long long* __restrict__ wsp, float bsq)
{
    __syncwarp();
    if (lane < 16){
        int j = kidx;
        float4 xj = sp4[j];
        float* gr = sgw + lane*20;
        gr[0]=xj.x-q.x; gr[1]=xj.y-q.y; gr[2]=xj.z-q.z;
        const float4* fr = reinterpret_cast<const float4*>(g_feat + ((size_t)b*1024 + j)*16);
        float4 f0=fr[0], f1=fr[1], f2v=fr[2], f3=fr[3];
        gr[3]=f0.x;  gr[4]=f0.y;  gr[5]=f0.z;  gr[6]=f0.w;
        gr[7]=f1.x;  gr[8]=f1.y;  gr[9]=f1.z;  gr[10]=f1.w;
        gr[11]=f2v.x; gr[12]=f2v.y; gr[13]=f2v.z; gr[14]=f2v.w;
        gr[15]=f3.x; gr[16]=f3.y; gr[17]=f3.z; gr[18]=f3.w;
    }
    __syncwarp();

    float mx = -BIGF;
    #pragma unroll 4
    for (int k=0;k<16;k++){
        const float* gr = sgw + k*20;
        ulonglong2 pA = *reinterpret_cast<const ulonglong2*>(gr);
        ulonglong2 pB = *reinterpret_cast<const ulonglong2*>(gr+4);
        ulonglong2 pC = *reinterpret_cast<const ulonglong2*>(gr+8);
        ulonglong2 pD = *reinterpret_cast<const ulonglong2*>(gr+12);
        unsigned long long pE = *reinterpret_cast<const unsigned long long*>(gr+16);
        float g18 = gr[18];
        unsigned long long acc = accp;
        acc = ffma2(pA.x, wp[0], acc);
        acc = ffma2(pA.y, wp[1], acc);
        acc = ffma2(pB.x, wp[2], acc);
        acc = ffma2(pB.y, wp[3], acc);
        acc = ffma2(pC.x, wp[4], acc);
        acc = ffma2(pC.y, wp[5], acc);
        acc = ffma2(pD.x, wp[6], acc);
        acc = ffma2(pD.y, wp[7], acc);
        acc = ffma2(pE,   wp[8], acc);
        float2 s = upk(acc);
        float a = fmaf(g18, wr18, s.x + s.y);
        mx = fmaxf(mx, lrelu(a));
    }

    smx[lane] = mx;
    __syncwarp();
    const unsigned long long* mp =
        reinterpret_cast<const unsigned long long*>(smx + cb);
    unsigned long long s2 = pk(0.f, 0.f);
    s2 = ffma2(mp[0], wsp[0], s2);
    s2 = ffma2(mp[1], wsp[1], s2);
    s2 = ffma2(mp[2], wsp[2], s2);
    s2 = ffma2(mp[3], wsp[3], s2);
    float2 sv = upk(s2);
    float s = sv.x + sv.y;
    s += __shfl_down_sync(FULLM, s, 16);
    s += __shfl_down_sync(FULLM, s, 8);
    if (lane < 8)
        g_fs[((size_t)b*512 + m)*8 + jq] = lrelu(s + bsq);
}

// ---------------------------------------------------------------------------
// Kernel B: pointconv1 (K=16 NN of 512 queries over 1024 pts) + fused squeeze
// grid (4, B): 128 queries per block, one warp handles 2 queries at a time.
// ---------------------------------------------------------------------------
__global__ void __launch_bounds__(256, 3) kB(
    const float* __restrict__ pc,
    const float* __restrict__ Wp, const float* __restrict__ bp,
    const float* __restrict__ Ws, const float* __restrict__ bsv)
{
    __shared__ __align__(16) float4 sp4[1024];
    __shared__ __align__(16) float  sg[8][16][20];
    __shared__ __align__(16) unsigned long long spA[8][32];
    __shared__ __align__(16) unsigned long long spB[8][32];
    __shared__ __align__(16) float  smx[8][32];

    int b    = blockIdx.y;
    int base = blockIdx.x * 128;
    int tid  = threadIdx.x;
    int lane = tid & 31;
    int w    = tid >> 5;

    const float* p = pc + (size_t)b*3072;
    for (int n = tid; n < 1024; n += 256){
        float X = p[n], Y = p[1024+n], Z = p[2048+n];
        sp4[n] = make_float4(X, Y, Z, fmaf(X,X, fmaf(Y,Y, Z*Z)));
    }
    __syncthreads();

    // packed per-lane GEMM weights: lane = output channel
    unsigned long long wp[9];
    #pragma unroll
    for (int c=0;c<9;c++)
        wp[c] = pk(__ldg(&Wp[(2*c)*32 + lane]), __ldg(&Wp[(2*c+1)*32 + lane]));
    float wr18 = __ldg(&Wp[18*32 + lane]);
    unsigned long long accp = pk(__ldg(&bp[lane]), 0.f);

    // squeeze weights: lane handles output j = lane&7 over c in [cb, cb+8)
    int jq = lane & 7, cb = (lane >> 3) * 8;
    unsigned long long wsp[4];
    #pragma unroll
    for (int i=0;i<4;i++)
        wsp[i] = pk(__ldg(&Ws[(cb+2*i)*8 + jq]), __ldg(&Ws[(cb+2*i+1)*8 + jq]));
    float bsq = __ldg(&bsv[jq]);

    for (int mp = 0; mp < 16; mp += 2){
        int mA = base + w + mp*8;
        int mB = mA + 8;
        float4 qa = sp4[2*mA];                        // xyz1[m] == xyz0[2m]
        float4 qb = sp4[2*mB];

        int kidxA, kidxB;
        knn16_dual<32>(sp4, qa, qb, lane, &spA[w][0], &spB[w][0], kidxA, kidxB);

        kb_tail(b, mA, qa, kidxA, lane, jq, cb, sp4, &sg[w][0][0], &smx[w][0],
                wp, wr18, accp, wsp, bsq);
        kb_tail(b, mB, qb, kidxB, lane, jq, cb, sp4, &sg[w][0][0], &smx[w][0],
                wp, wr18, accp, wsp, bsq);
    }
}

// ---------------------------------------------------------------------------
// kC per-query tail: gather + GEMM (4 out-channels/lane) + accumulate
// ---------------------------------------------------------------------------
__device__ __forceinline__ void kc_tail(
    float4 q, int kidx, int lane,
    const float4* __restrict__ sp4, const float* __restrict__ sf,
    float* __restrict__ sgw,
    const unsigned long long* __restrict__ wq0,
    const unsigned long long* __restrict__ wq1,
    const unsigned long long* __restrict__ wq2,
    const unsigned long long* __restrict__ wq3,
    float w10_0, float w10_1, float w10_2, float w10_3,
    unsigned long long bp0, unsigned long long bp1,
    unsigned long long bp2, unsigned long long bp3,
    float& acc0, float& acc1, float& acc2, float& acc3)
{
    __syncwarp();
    if (lane < 16){
        int j = kidx;
        float4 xj = sp4[j];
        float* gr = sgw + lane*12;
        gr[0]=xj.x-q.x; gr[1]=xj.y-q.y; gr[2]=xj.z-q.z;
        const float4* fr = reinterpret_cast<const float4*>(sf + j*8);
        float4 f0=fr[0], f1=fr[1];
        gr[3]=f0.x; gr[4]=f0.y; gr[5]=f0.z; gr[6]=f0.w;
        gr[7]=f1.x; gr[8]=f1.y; gr[9]=f1.z; gr[10]=f1.w;
    }
    __syncwarp();

    float mx0=-BIGF, mx1=-BIGF, mx2=-BIGF, mx3=-BIGF;
    #pragma unroll 4
    for (int k=0;k<16;k++){
        const float* gr = sgw + k*12;
        ulonglong2 pA = *reinterpret_cast<const ulonglong2*>(gr);
        ulonglong2 pB = *reinterpret_cast<const ulonglong2*>(gr+4);
        float4     v2 = *reinterpret_cast<const float4*>(gr+8);
        unsigned long long p4 = pk(v2.x, v2.y);
        float g10 = v2.z;
        unsigned long long a0=bp0, a1=bp1, a2=bp2, a3=bp3;
        a0 = ffma2(pA.x, wq0[0], a0); a1 = ffma2(pA.x, wq1[0], a1);
        a2 = ffma2(pA.x, wq2[0], a2); a3 = ffma2(pA.x, wq3[0], a3);
        a0 = ffma2(pA.y, wq0[1], a0); a1 = ffma2(pA.y, wq1[1], a1);
        a2 = ffma2(pA.y, wq2[1], a2); a3 = ffma2(pA.y, wq3[1], a3);
        a0 = ffma2(pB.x, wq0[2], a0); a1 = ffma2(pB.x, wq1[2], a1);
        a2 = ffma2(pB.x, wq2[2], a2); a3 = ffma2(pB.x, wq3[2], a3);
        a0 = ffma2(pB.y, wq0[3], a0); a1 = ffma2(pB.y, wq1[3], a1);
        a2 = ffma2(pB.y, wq2[3], a2); a3 = ffma2(pB.y, wq3[3], a3);
        a0 = ffma2(p4,   wq0[4], a0); a1 = ffma2(p4,   wq1[4], a1);
        a2 = ffma2(p4,   wq2[4], a2); a3 = ffma2(p4,   wq3[4], a3);
        float2 s0 = upk(a0), s1 = upk(a1), s2 = upk(a2), s3 = upk(a3);
        float r0 = fmaf(g10, w10_0, s0.x + s0.y);
        float r1 = fmaf(g10, w10_1, s1.x + s1.y);
        float r2 = fmaf(g10, w10_2, s2.x + s2.y);
        float r3 = fmaf(g10, w10_3, s3.x + s3.y);
        mx0 = fmaxf(mx0, lrelu(r0));
        mx1 = fmaxf(mx1, lrelu(r1));
        mx2 = fmaxf(mx2, lrelu(r2));
        mx3 = fmaxf(mx3, lrelu(r3));
    }
    acc0 += mx0; acc1 += mx1; acc2 += mx2; acc3 += mx3;
}

// ---------------------------------------------------------------------------
// Kernel C: pointconv2 (128 queries, 512 candidates, 11ch -> 128ch),
// fused column-sum. grid (2, B): 64 queries/block, 2 queries per warp iter.
// ---------------------------------------------------------------------------
__global__ void __launch_bounds__(256, 3) kC(
    const float* __restrict__ pc,
    const float* __restrict__ Wc, const float* __restrict__ bc)
{
    __shared__ __align__(16) float4 sp4[512];
    __shared__ __align__(16) float  sf[512*8];
    __shared__ __align__(16) float  sg[8][16][12];
    __shared__ __align__(16) unsigned long long spA[8][32];
    __shared__ __align__(16) unsigned long long spB[8][32];
    __shared__ float  sacc[8][128];

    int b    = blockIdx.y;
    int base = blockIdx.x * 64;
    int tid  = threadIdx.x;
    int lane = tid & 31;
    int w    = tid >> 5;

    const float* p = pc + (size_t)b*3072;
    for (int m = tid; m < 512; m += 256){
        float X = p[2*m], Y = p[1024+2*m], Z = p[2048+2*m]; // xyz1[m]=xyz0[2m]
        sp4[m] = make_float4(X, Y, Z, fmaf(X,X, fmaf(Y,Y, Z*Z)));
    }
    {
        const float4* src = reinterpret_cast<const float4*>(g_fs + (size_t)b*4096);
        float4* dst = reinterpret_cast<float4*>(sf);
        for (int t = tid; t < 1024; t += 256) dst[t] = src[t];
    }
    __syncthreads();

    unsigned long long wq0[5], wq1[5], wq2[5], wq3[5];
    #pragma unroll
    for (int c=0;c<5;c++){
        wq0[c] = pk(__ldg(&Wc[(2*c)*128 + lane]),      __ldg(&Wc[(2*c+1)*128 + lane]));
        wq1[c] = pk(__ldg(&Wc[(2*c)*128 + lane + 32]), __ldg(&Wc[(2*c+1)*128 + lane + 32]));
        wq2[c] = pk(__ldg(&Wc[(2*c)*128 + lane + 64]), __ldg(&Wc[(2*c+1)*128 + lane + 64]));
        wq3[c] = pk(__ldg(&Wc[(2*c)*128 + lane + 96]), __ldg(&Wc[(2*c+1)*128 + lane + 96]));
    }
    float w10_0 = __ldg(&Wc[10*128 + lane]),      w10_1 = __ldg(&Wc[10*128 + lane + 32]);
    float w10_2 = __ldg(&Wc[10*128 + lane + 64]), w10_3 = __ldg(&Wc[10*128 + lane + 96]);
    unsigned long long bp0 = pk(__ldg(&bc[lane]),     0.f);
    unsigned long long bp1 = pk(__ldg(&bc[lane+32]),  0.f);
    unsigned long long bp2 = pk(__ldg(&bc[lane+64]),  0.f);
    unsigned long long bp3 = pk(__ldg(&bc[lane+96]),  0.f);

    float acc0 = 0.f, acc1 = 0.f, acc2 = 0.f, acc3 = 0.f;

    for (int mp = 0; mp < 8; mp += 2){
        int mA = base + w + mp*8;
        int mB = mA + 8;
        float4 qa = sp4[4*mA];                        // xyz2[m2] == xyz1[4*m2]
        float4 qb = sp4[4*mB];

        int kidxA, kidxB;
        knn16_dual<16>(sp4, qa, qb, lane, &spA[w][0], &spB[w][0], kidxA, kidxB);

        kc_tail(qa, kidxA, lane, sp4, sf, &sg[w][0][0],
                wq0, wq1, wq2, wq3, w10_0, w10_1, w10_2, w10_3,
                bp0, bp1, bp2, bp3, acc0, acc1, acc2, acc3);
        kc_tail(qb, kidxB, lane, sp4, sf, &sg[w][0][0],
                wq0, wq1, wq2, wq3, w10_0, w10_1, w10_2, w10_3,
                bp0, bp1, bp2, bp3, acc0, acc1, acc2, acc3);
    }

    sacc[w][lane]      = acc0;
    sacc[w][lane + 32] = acc1;
    sacc[w][lane + 64] = acc2;
    sacc[w][lane + 96] = acc3;
    __syncthreads();
    if (tid < 128){
        float s = sacc[0][tid];
        #pragma unroll
        for (int ww=1; ww<8; ww++) s += sacc[ww][tid];
        g_psum[((size_t)b*2 + blockIdx.x)*128 + tid] = s;
    }
}

// ---------------------------------------------------------------------------
// Kernel D: out[b] = (psum0+psum1)/128 @ We + be
// ---------------------------------------------------------------------------
__global__ void __launch_bounds__(256) kD(
    const float* __restrict__ We, const float* __restrict__ be,
    float* __restrict__ out)
{
    __shared__ float sbar[128];
    int b = blockIdx.x, tid = threadIdx.x;
    if (tid < 128){
        float s = g_psum[((size_t)b*2)*128 + tid] + g_psum[((size_t)b*2+1)*128 + tid];
        sbar[tid] = s * (1.f/128.f);
    }
    __syncthreads();
    float acc = __ldg(&be[tid]);
    #pragma unroll 8
    for (int c=0;c<128;c++) acc = fmaf(sbar[c], __ldg(&We[c*256 + tid]), acc);
    out[(size_t)b*256 + tid] = acc;
}

// ---------------------------------------------------------------------------
extern "C" void kernel_launch(void* const* d_in, const int* in_sizes, int n_in,
                              void* d_out, int out_size)
{
    (void)in_sizes; (void)n_in; (void)out_size;
    const float* pc  = (const float*)d_in[0];
    const float* W0  = (const float*)d_in[1];
    const float* b0  = (const float*)d_in[2];
    const float* g0  = (const float*)d_in[3];
    const float* be0 = (const float*)d_in[4];
    const float* W1  = (const float*)d_in[5];
    const float* b1  = (const float*)d_in[6];
    const float* g1  = (const float*)d_in[7];
    const float* be1 = (const float*)d_in[8];
    const float* Wp  = (const float*)d_in[9];
    const float* bp  = (const float*)d_in[10];
    const float* Ws  = (const float*)d_in[11];
    const float* bsv = (const float*)d_in[12];
    const float* Wc  = (const float*)d_in[13];
    const float* bc  = (const float*)d_in[14];
    const float* We  = (const float*)d_in[15];
    const float* be  = (const float*)d_in[16];
    float* out = (float*)d_out;

    kA<<<1024, 256>>>(pc, W0, b0, g0, be0, W1, b1, g1, be1);
    dim3 gB(4, 256);
    kB<<<gB, 256>>>(pc, Wp, bp, Ws, bsv);
    dim3 gC(2, 256);
    kC<<<gC, 256>>>(pc, Wc, bc);
    kD<<<256, 256>>>(We, be, out);
}

// round 9
// speedup vs baseline: 2.6369x; 2.6369x over previous
#include <cuda_runtime.h>
#include <cstdint>

#define FULLM 0xFFFFFFFFu
#define BIGF  3.402823466e+38f

__device__ float g_feat[256*1024*16]; // stage-1 per-point features (B,N,16)
__device__ float g_fs[256*512*8];     // squeezed features on xyz1 (B,512,8)
__device__ float g_psum[256*4*128];   // per-block partial sums of f2 (B,4,128)

__device__ __forceinline__ float lrelu(float x){ return x > 0.f ? x : 0.2f*x; }

// ---- packed f32x2 helpers (Blackwell) -------------------------------------
__device__ __forceinline__ unsigned long long pk(float lo, float hi){
    unsigned long long r;
    asm("mov.b64 %0, {%1, %2};" : "=l"(r) : "f"(lo), "f"(hi));
    return r;
}
__device__ __forceinline__ float2 upk(unsigned long long v){
    float2 r;
    asm("mov.b64 {%0, %1}, %2;" : "=f"(r.x), "=f"(r.y) : "l"(v));
    return r;
}
__device__ __forceinline__ unsigned long long ffma2(
    unsigned long long a, unsigned long long b, unsigned long long c){
    unsigned long long d;
    asm("fma.rn.f32x2 %0, %1, %2, %3;" : "=l"(d) : "l"(a), "l"(b), "l"(c));
    return d;
}

__device__ __forceinline__ float qdist(const float4& v, float qx, float qy, float qz){
    // d' = |p|^2 - 2 q.p  (query-constant |q|^2 dropped: order-preserving)
    return fmaf(-2.f, fmaf(qx, v.x, fmaf(qy, v.y, qz*v.z)), v.w);
}

// Value-only bitonic sort of 32 floats across a warp (ascending).
__device__ __forceinline__ float bsort32_val(float s, int lane){
    #pragma unroll
    for (int k = 2; k <= 32; k <<= 1){
        #pragma unroll
        for (int j = k >> 1; j > 0; j >>= 1){
            float o = __shfl_xor_sync(FULLM, s, j);
            bool keepmin = ((lane & j) == 0) == ((lane & k) == 0);
            float mn = fminf(s, o), mx = fmaxf(s, o);
            s = keepmin ? mn : mx;
        }
    }
    return s;
}

// Bitonic sort of 32 (d,i) pairs across a warp, ascending lex (d, then i).
__device__ __forceinline__ void bsort32_pair(float& d, int& i, int lane){
    #pragma unroll
    for (int k = 2; k <= 32; k <<= 1){
        #pragma unroll
        for (int j = k >> 1; j > 0; j >>= 1){
            float od = __shfl_xor_sync(FULLM, d, j);
            int   oi = __shfl_xor_sync(FULLM, i, j);
            bool lower = (lane & j) == 0;
            bool asc   = (lane & k) == 0;
            bool osm   = (od < d) || (od == d && oi < i);
            bool take  = (lower == asc) ? osm : !osm;
            if (take){ d = od; i = oi; }
        }
    }
}

// Exact top-16 of NT*32 candidates. sp holds (x,y,z,|p|^2) per point.
// Returns the set of 16 nearest indices distributed on lanes 0..15
// (arbitrary order — callers only max-pool over the set).
template<int NT>
__device__ __forceinline__ int knn16_select(
    const float4* __restrict__ sp,
    float qx, float qy, float qz, int lane,
    float* scand, int* sidxs)
{
    // --- phase 1: per-lane min distance (4 independent chains) -------------
    float m0 = BIGF, m1 = BIGF, m2 = BIGF, m3 = BIGF;
    #pragma unroll
    for (int t = 0; t < NT; t += 4){
        float d0 = qdist(sp[lane + (t  )*32], qx, qy, qz);
        float d1 = qdist(sp[lane + (t+1)*32], qx, qy, qz);
        float d2 = qdist(sp[lane + (t+2)*32], qx, qy, qz);
        float d3 = qdist(sp[lane + (t+3)*32], qx, qy, qz);
        m0 = fminf(m0, d0); m1 = fminf(m1, d1);
        m2 = fminf(m2, d2); m3 = fminf(m3, d3);
    }
    float bd = fminf(fminf(m0, m1), fminf(m2, m3));

    // --- phase 2: threshold = 16th-smallest lane minimum (valid bound) -----
    float thr = __shfl_sync(FULLM, bsort32_val(bd, lane), 15);

    // --- phase 3: recompute + ballot-compact all d <= thr ------------------
    scand[lane] = BIGF; sidxs[lane] = 0x7FFFFFFF;
    __syncwarp();
    unsigned lt = (1u << lane) - 1u;
    int cnt = 0;
    #pragma unroll
    for (int t = 0; t < NT; t++){
        float d = qdist(sp[lane + t*32], qx, qy, qz);
        bool p = (d <= thr);
        unsigned mask = __ballot_sync(FULLM, p);
        if (p){
            int pos = cnt + __popc(mask & lt);
            if (pos < 32){ scand[pos] = d; sidxs[pos] = lane + t*32; }
        }
        cnt += __popc(mask);
    }
    __syncwarp();

    int kidx;
    if (cnt <= 32){
        float d2 = scand[lane]; int i2 = sidxs[lane];
        // value-only sort to find the 16th-smallest distance in the buffer
        float thr16 = __shfl_sync(FULLM, bsort32_val(d2, lane), 15);
        unsigned sel = __ballot_sync(FULLM, d2 <= thr16);
        if (__popc(sel) == 16){
            // no boundary tie: selected lanes ARE the exact top-16 set
            __syncwarp();
            if (d2 <= thr16){
                int pos = __popc(sel & lt);
                sidxs[pos] = i2;
            }
            __syncwarp();
            kidx = sidxs[lane & 15];
        } else {
            // boundary tie on distance: exact lex (d, idx) sort
            bsort32_pair(d2, i2, lane);
            kidx = i2;
        }
    } else {
        // --- rare fallback: progressive argmin with lex exclusion ----------
        float lastD = -BIGF; int lastI = -1; kidx = 0x7FFFFFFF;
        for (int r = 0; r < 16; r++){
            float cbd = BIGF; int cbi = 0x7FFFFFFF;
            #pragma unroll
            for (int t = 0; t < NT; t++){
                int j = lane + t*32;
                float d = qdist(sp[j], qx, qy, qz);
                bool gt = (d > lastD) || (d == lastD && j > lastI);
                if (gt && ((d < cbd) || (d == cbd && j < cbi))){ cbd = d; cbi = j; }
            }
            #pragma unroll
            for (int off = 16; off > 0; off >>= 1){
                float od = __shfl_down_sync(FULLM, cbd, off);
                int   oi = __shfl_down_sync(FULLM, cbi, off);
                if (od < cbd || (od == cbd && oi < cbi)){ cbd = od; cbi = oi; }
            }
            lastD = __shfl_sync(FULLM, cbd, 0);
            lastI = __shfl_sync(FULLM, cbi, 0);
            if (lane == r) kidx = lastI;
        }
    }
    return kidx;
}

// ---------------------------------------------------------------------------
// Kernel A: f = lrelu(LN(lrelu(LN(xyz@W0+b0))@W1+b1))  per point
// ---------------------------------------------------------------------------
__global__ void __launch_bounds__(256) kA(
    const float* __restrict__ pc,
    const float* __restrict__ W0, const float* __restrict__ b0,
    const float* __restrict__ g0, const float* __restrict__ be0,
    const float* __restrict__ W1, const float* __restrict__ b1,
    const float* __restrict__ g1, const float* __restrict__ be1)
{
    int i = blockIdx.x*256 + threadIdx.x;
    int b = i >> 10, n = i & 1023;
    const float* p = pc + (size_t)b*3072;
    float x = p[n], y = p[1024+n], z = p[2048+n];

    float t[16];
    #pragma unroll
    for (int c=0;c<16;c++)
        t[c] = fmaf(x, __ldg(&W0[c]), fmaf(y, __ldg(&W0[16+c]), fmaf(z, __ldg(&W0[32+c]), __ldg(&b0[c]))));
    {
        float m=0.f;
        #pragma unroll
        for (int c=0;c<16;c++) m += t[c];
        m *= (1.f/16.f);
        float v=0.f;
        #pragma unroll
        for (int c=0;c<16;c++){ float dd=t[c]-m; v = fmaf(dd,dd,v); }
        v *= (1.f/16.f);
        float inv = rsqrtf(v + 1e-5f);
        #pragma unroll
        for (int c=0;c<16;c++)
            t[c] = lrelu(fmaf((t[c]-m)*inv, __ldg(&g0[c]), __ldg(&be0[c])));
    }
    float u[16];
    #pragma unroll
    for (int o=0;o<16;o++){
        float a = __ldg(&b1[o]);
        #pragma unroll
        for (int c=0;c<16;c++) a = fmaf(t[c], __ldg(&W1[c*16+o]), a);
        u[o] = a;
    }
    {
        float m=0.f;
        #pragma unroll
        for (int c=0;c<16;c++) m += u[c];
        m *= (1.f/16.f);
        float v=0.f;
        #pragma unroll
        for (int c=0;c<16;c++){ float dd=u[c]-m; v = fmaf(dd,dd,v); }
        v *= (1.f/16.f);
        float inv = rsqrtf(v + 1e-5f);
        #pragma unroll
        for (int c=0;c<16;c++)
            u[c] = lrelu(fmaf((u[c]-m)*inv, __ldg(&g1[c]), __ldg(&be1[c])));
    }
    float4* o4 = reinterpret_cast<float4*>(g_feat + (size_t)i*16);
    o4[0] = make_float4(u[0],u[1],u[2],u[3]);
    o4[1] = make_float4(u[4],u[5],u[6],u[7]);
    o4[2] = make_float4(u[8],u[9],u[10],u[11]);
    o4[3] = make_float4(u[12],u[13],u[14],u[15]);
}

// ---------------------------------------------------------------------------
// Kernel B: pointconv1 (K=16 NN of 512 queries over 1024 pts) + fused squeeze
// grid (8, B): 64 queries per block, one warp per query (finer blocks to
// reduce wave-quantization tail at occupancy 3 blocks/SM).
// ---------------------------------------------------------------------------
__global__ void __launch_bounds__(256, 3) kB(
    const float* __restrict__ pc,
    const float* __restrict__ Wp, const float* __restrict__ bp,
    const float* __restrict__ Ws, const float* __restrict__ bsv)
{
    __shared__ __align__(16) float4 sp4[1024];
    __shared__ __align__(16) float  sg[8][16][20];
    __shared__ __align__(16) float  scand[8][32];
    __shared__ __align__(16) int    sidxs[8][32];
    __shared__ __align__(16) float  smx[8][32];

    int b    = blockIdx.y;
    int base = blockIdx.x * 64;
    int tid  = threadIdx.x;
    int lane = tid & 31;
    int w    = tid >> 5;

    const float* p = pc + (size_t)b*3072;
    for (int n = tid; n < 1024; n += 256){
        float X = p[n], Y = p[1024+n], Z = p[2048+n];
        sp4[n] = make_float4(X, Y, Z, fmaf(X,X, fmaf(Y,Y, Z*Z)));
    }
    __syncthreads();

    // packed per-lane GEMM weights: lane = output channel
    unsigned long long wp[9];
    #pragma unroll
    for (int c=0;c<9;c++)
        wp[c] = pk(__ldg(&Wp[(2*c)*32 + lane]), __ldg(&Wp[(2*c+1)*32 + lane]));
    float wr18 = __ldg(&Wp[18*32 + lane]);
    unsigned long long accp = pk(__ldg(&bp[lane]), 0.f);

    // squeeze weights: lane handles output j = lane&7 over c in [cb, cb+8)
    int jq = lane & 7, cb = (lane >> 3) * 8;
    unsigned long long wsp[4];
    #pragma unroll
    for (int i=0;i<4;i++)
        wsp[i] = pk(__ldg(&Ws[(cb+2*i)*8 + jq]), __ldg(&Ws[(cb+2*i+1)*8 + jq]));
    float bsq = __ldg(&bsv[jq]);

    for (int m = base + w; m < base + 64; m += 8){
        int qi = 2*m;                                   // xyz1[m] == xyz0[2m]
        float4 q = sp4[qi];

        int kidx = knn16_select<32>(sp4, q.x, q.y, q.z, lane,
                                    &scand[w][0], &sidxs[w][0]);

        // --- gather neighbors into per-warp smem g[16][20] ------------------
        __syncwarp();
        if (lane < 16){
            int j = kidx;
            float4 xj = sp4[j];
            float* gr = &sg[w][lane][0];
            gr[0]=xj.x-q.x; gr[1]=xj.y-q.y; gr[2]=xj.z-q.z;
            const float4* fr = reinterpret_cast<const float4*>(g_feat + ((size_t)b*1024 + j)*16);
            float4 f0=fr[0], f1=fr[1], f2v=fr[2], f3=fr[3];
            gr[3]=f0.x;  gr[4]=f0.y;  gr[5]=f0.z;  gr[6]=f0.w;
            gr[7]=f1.x;  gr[8]=f1.y;  gr[9]=f1.z;  gr[10]=f1.w;
            gr[11]=f2v.x; gr[12]=f2v.y; gr[13]=f2v.z; gr[14]=f2v.w;
            gr[15]=f3.x; gr[16]=f3.y; gr[17]=f3.z; gr[18]=f3.w;
        }
        __syncwarp();

        // --- GEMM (lane = output channel) via packed FFMA2 + maxpool -------
        float mx = -BIGF;
        #pragma unroll 4
        for (int k=0;k<16;k++){
            const float* gr = &sg[w][k][0];
            ulonglong2 pA = *reinterpret_cast<const ulonglong2*>(gr);
            ulonglong2 pB = *reinterpret_cast<const ulonglong2*>(gr+4);
            ulonglong2 pC = *reinterpret_cast<const ulonglong2*>(gr+8);
            ulonglong2 pD = *reinterpret_cast<const ulonglong2*>(gr+12);
            unsigned long long pE = *reinterpret_cast<const unsigned long long*>(gr+16);
            float  g18 = gr[18];
            unsigned long long acc = accp;
            acc = ffma2(pA.x, wp[0], acc);
            acc = ffma2(pA.y, wp[1], acc);
            acc = ffma2(pB.x, wp[2], acc);
            acc = ffma2(pB.y, wp[3], acc);
            acc = ffma2(pC.x, wp[4], acc);
            acc = ffma2(pC.y, wp[5], acc);
            acc = ffma2(pD.x, wp[6], acc);
            acc = ffma2(pD.y, wp[7], acc);
            acc = ffma2(pE,   wp[8], acc);
            float2 s = upk(acc);
            float a = fmaf(g18, wr18, s.x + s.y);
            mx = fmaxf(mx, lrelu(a));
        }

        // --- fused squeeze via smem transpose: fs = lrelu(mx @ Ws + bs) -----
        smx[w][lane] = mx;
        __syncwarp();
        const unsigned long long* mp =
            reinterpret_cast<const unsigned long long*>(&smx[w][cb]);
        unsigned long long s2 = pk(0.f, 0.f);
        s2 = ffma2(mp[0], wsp[0], s2);
        s2 = ffma2(mp[1], wsp[1], s2);
        s2 = ffma2(mp[2], wsp[2], s2);
        s2 = ffma2(mp[3], wsp[3], s2);
        float2 sv = upk(s2);
        float s = sv.x + sv.y;
        s += __shfl_down_sync(FULLM, s, 16);
        s += __shfl_down_sync(FULLM, s, 8);
        if (lane < 8)
            g_fs[((size_t)b*512 + m)*8 + jq] = lrelu(s + bsq);
    }
}

// ---------------------------------------------------------------------------
// Kernel C: pointconv2 (128 queries, 512 candidates, 11ch -> 128ch),
// fused column-sum (mean commutes with the final linear map).
// grid (4, B): 32 queries per block, one warp per query (finer blocks).
// ---------------------------------------------------------------------------
__global__ void __launch_bounds__(256, 3) kC(
    const float* __restrict__ pc,
    const float* __restrict__ Wc, const float* __restrict__ bc)
{
    __shared__ __align__(16) float4 sp4[512];
    __shared__ __align__(16) float  sf[512*8];
    __shared__ __align__(16) float  sg[8][16][12];
    __shared__ __align__(16) float  scand[8][32];
    __shared__ __align__(16) int    sidxs[8][32];
    __shared__ float  sacc[8][128];

    int b    = blockIdx.y;
    int base = blockIdx.x * 32;
    int tid  = threadIdx.x;
    int lane = tid & 31;
    int w    = tid >> 5;

    const float* p = pc + (size_t)b*3072;
    for (int m = tid; m < 512; m += 256){
        float X = p[2*m], Y = p[1024+2*m], Z = p[2048+2*m]; // xyz1[m]=xyz0[2m]
        sp4[m] = make_float4(X, Y, Z, fmaf(X,X, fmaf(Y,Y, Z*Z)));
    }
    {
        const float4* src = reinterpret_cast<const float4*>(g_fs + (size_t)b*4096);
        float4* dst = reinterpret_cast<float4*>(sf);
        for (int t = tid; t < 1024; t += 256) dst[t] = src[t];
    }
    __syncthreads();

    // packed weights for 4 output channels per lane (lane, lane+32, +64, +96)
    unsigned long long wq0[5], wq1[5], wq2[5], wq3[5];
    #pragma unroll
    for (int c=0;c<5;c++){
        wq0[c] = pk(__ldg(&Wc[(2*c)*128 + lane]),      __ldg(&Wc[(2*c+1)*128 + lane]));
        wq1[c] = pk(__ldg(&Wc[(2*c)*128 + lane + 32]), __ldg(&Wc[(2*c+1)*128 + lane + 32]));
        wq2[c] = pk(__ldg(&Wc[(2*c)*128 + lane + 64]), __ldg(&Wc[(2*c+1)*128 + lane + 64]));
        wq3[c] = pk(__ldg(&Wc[(2*c)*128 + lane + 96]), __ldg(&Wc[(2*c+1)*128 + lane + 96]));
    }
    float w10_0 = __ldg(&Wc[10*128 + lane]),      w10_1 = __ldg(&Wc[10*128 + lane + 32]);
    float w10_2 = __ldg(&Wc[10*128 + lane + 64]), w10_3 = __ldg(&Wc[10*128 + lane + 96]);
    unsigned long long bp0 = pk(__ldg(&bc[lane]),     0.f);
    unsigned long long bp1 = pk(__ldg(&bc[lane+32]),  0.f);
    unsigned long long bp2 = pk(__ldg(&bc[lane+64]),  0.f);
    unsigned long long bp3 = pk(__ldg(&bc[lane+96]),  0.f);

    float acc0 = 0.f, acc1 = 0.f, acc2 = 0.f, acc3 = 0.f;

    for (int m2 = base + w; m2 < base + 32; m2 += 8){
        int qi = 4*m2;                                  // xyz2[m2] == xyz1[4*m2]
        float4 q = sp4[qi];

        int kidx = knn16_select<16>(sp4, q.x, q.y, q.z, lane,
                                    &scand[w][0], &sidxs[w][0]);

        __syncwarp();
        if (lane < 16){
            int j = kidx;
            float4 xj = sp4[j];
            float* gr = &sg[w][lane][0];
            gr[0]=xj.x-q.x; gr[1]=xj.y-q.y; gr[2]=xj.z-q.z;
            const float4* fr = reinterpret_cast<const float4*>(sf + j*8);
            float4 f0=fr[0], f1=fr[1];
            gr[3]=f0.x; gr[4]=f0.y; gr[5]=f0.z; gr[6]=f0.w;
            gr[7]=f1.x; gr[8]=f1.y; gr[9]=f1.z; gr[10]=f1.w;
        }
        __syncwarp();

        float mx0=-BIGF, mx1=-BIGF, mx2=-BIGF, mx3=-BIGF;
        #pragma unroll 4
        for (int k=0;k<16;k++){
            const float* gr = &sg[w][k][0];
            ulonglong2 pA = *reinterpret_cast<const ulonglong2*>(gr);     // g0..g3
            ulonglong2 pB = *reinterpret_cast<const ulonglong2*>(gr+4);   // g4..g7
            float4     v2 = *reinterpret_cast<const float4*>(gr+8);       // g8..g11(pad)
            unsigned long long p4 = pk(v2.x, v2.y);
            float g10 = v2.z;
            unsigned long long a0=bp0, a1=bp1, a2=bp2, a3=bp3;
            a0 = ffma2(pA.x, wq0[0], a0); a1 = ffma2(pA.x, wq1[0], a1);
            a2 = ffma2(pA.x, wq2[0], a2); a3 = ffma2(pA.x, wq3[0], a3);
            a0 = ffma2(pA.y, wq0[1], a0); a1 = ffma2(pA.y, wq1[1], a1);
            a2 = ffma2(pA.y, wq2[1], a2); a3 = ffma2(pA.y, wq3[1], a3);
            a0 = ffma2(pB.x, wq0[2], a0); a1 = ffma2(pB.x, wq1[2], a1);
            a2 = ffma2(pB.x, wq2[2], a2); a3 = ffma2(pB.x, wq3[2], a3);
            a0 = ffma2(pB.y, wq0[3], a0); a1 = ffma2(pB.y, wq1[3], a1);
            a2 = ffma2(pB.y, wq2[3], a2); a3 = ffma2(pB.y, wq3[3], a3);
            a0 = ffma2(p4,   wq0[4], a0); a1 = ffma2(p4,   wq1[4], a1);
            a2 = ffma2(p4,   wq2[4], a2); a3 = ffma2(p4,   wq3[4], a3);
            float2 s0 = upk(a0), s1 = upk(a1), s2 = upk(a2), s3 = upk(a3);
            float r0 = fmaf(g10, w10_0, s0.x + s0.y);
            float r1 = fmaf(g10, w10_1, s1.x + s1.y);
            float r2 = fmaf(g10, w10_2, s2.x + s2.y);
            float r3 = fmaf(g10, w10_3, s3.x + s3.y);
            mx0 = fmaxf(mx0, lrelu(r0));
            mx1 = fmaxf(mx1, lrelu(r1));
            mx2 = fmaxf(mx2, lrelu(r2));
            mx3 = fmaxf(mx3, lrelu(r3));
        }
        acc0 += mx0; acc1 += mx1; acc2 += mx2; acc3 += mx3;
    }

    // deterministic in-block reduction of per-warp partial sums
    sacc[w][lane]      = acc0;
    sacc[w][lane + 32] = acc1;
    sacc[w][lane + 64] = acc2;
    sacc[w][lane + 96] = acc3;
    __syncthreads();
    if (tid < 128){
        float s = sacc[0][tid];
        #pragma unroll
        for (int ww=1; ww<8; ww++) s += sacc[ww][tid];
        g_psum[((size_t)b*4 + blockIdx.x)*128 + tid] = s;
    }
}

// ---------------------------------------------------------------------------
// Kernel D: out[b] = (sum of 4 psums)/128 @ We + be
// ---------------------------------------------------------------------------
__global__ void __launch_bounds__(256) kD(
    const float* __restrict__ We, const float* __restrict__ be,
    float* __restrict__ out)
{
    __shared__ float sbar[128];
    int b = blockIdx.x, tid = threadIdx.x;
    if (tid < 128){
        const float* ps = g_psum + (size_t)b*4*128 + tid;
        float s = (ps[0] + ps[128]) + (ps[256] + ps[384]);
        sbar[tid] = s * (1.f/128.f);
    }
    __syncthreads();
    float acc = __ldg(&be[tid]);
    #pragma unroll 8
    for (int c=0;c<128;c++) acc = fmaf(sbar[c], __ldg(&We[c*256 + tid]), acc);
    out[(size_t)b*256 + tid] = acc;
}

// ---------------------------------------------------------------------------
extern "C" void kernel_launch(void* const* d_in, const int* in_sizes, int n_in,
                              void* d_out, int out_size)
{
    (void)in_sizes; (void)n_in; (void)out_size;
    const float* pc  = (const float*)d_in[0];
    const float* W0  = (const float*)d_in[1];
    const float* b0  = (const float*)d_in[2];
    const float* g0  = (const float*)d_in[3];
    const float* be0 = (const float*)d_in[4];
    const float* W1  = (const float*)d_in[5];
    const float* b1  = (const float*)d_in[6];
    const float* g1  = (const float*)d_in[7];
    const float* be1 = (const float*)d_in[8];
    const float* Wp  = (const float*)d_in[9];
    const float* bp  = (const float*)d_in[10];
    const float* Ws  = (const float*)d_in[11];
    const float* bsv = (const float*)d_in[12];
    const float* Wc  = (const float*)d_in[13];
    const float* bc  = (const float*)d_in[14];
    const float* We  = (const float*)d_in[15];
    const float* be  = (const float*)d_in[16];
    float* out = (float*)d_out;

    kA<<<1024, 256>>>(pc, W0, b0, g0, be0, W1, b1, g1, be1);
    dim3 gB(8, 256);
    kB<<<gB, 256>>>(pc, Wp, bp, Ws, bsv);
    dim3 gC(4, 256);
    kC<<<gC, 256>>>(pc, Wc, bc);
    kD<<<256, 256>>>(We, be, out);
}

// round 10
// speedup vs baseline: 2.7011x; 1.0243x over previous
#include <cuda_runtime.h>
#include <cstdint>

#define FULLM 0xFFFFFFFFu
#define BIGF  3.402823466e+38f

__device__ float g_feat[256*1024*16]; // stage-1 per-point features (B,N,16)
__device__ float g_fs[256*512*8];     // squeezed features on xyz1 (B,512,8)
__device__ float g_psum[256*16*128];  // per-chunk partial sums of f2 (B,16,128)

__device__ __forceinline__ float lrelu(float x){ return x > 0.f ? x : 0.2f*x; }

// ---- packed f32x2 helpers (Blackwell) -------------------------------------
__device__ __forceinline__ unsigned long long pk(float lo, float hi){
    unsigned long long r;
    asm("mov.b64 %0, {%1, %2};" : "=l"(r) : "f"(lo), "f"(hi));
    return r;
}
__device__ __forceinline__ float2 upk(unsigned long long v){
    float2 r;
    asm("mov.b64 {%0, %1}, %2;" : "=f"(r.x), "=f"(r.y) : "l"(v));
    return r;
}
__device__ __forceinline__ unsigned long long ffma2(
    unsigned long long a, unsigned long long b, unsigned long long c){
    unsigned long long d;
    asm("fma.rn.f32x2 %0, %1, %2, %3;" : "=l"(d) : "l"(a), "l"(b), "l"(c));
    return d;
}

__device__ __forceinline__ float qdist(const float4& v, float qx, float qy, float qz){
    // d' = |p|^2 - 2 q.p  (query-constant |q|^2 dropped: order-preserving)
    return fmaf(-2.f, fmaf(qx, v.x, fmaf(qy, v.y, qz*v.z)), v.w);
}

// Value-only bitonic sort of 32 floats across a warp (ascending).
__device__ __forceinline__ float bsort32_val(float s, int lane){
    #pragma unroll
    for (int k = 2; k <= 32; k <<= 1){
        #pragma unroll
        for (int j = k >> 1; j > 0; j >>= 1){
            float o = __shfl_xor_sync(FULLM, s, j);
            bool keepmin = ((lane & j) == 0) == ((lane & k) == 0);
            float mn = fminf(s, o), mx = fmaxf(s, o);
            s = keepmin ? mn : mx;
        }
    }
    return s;
}

// Bitonic sort of 32 (d,i) pairs across a warp, ascending lex (d, then i).
__device__ __forceinline__ void bsort32_pair(float& d, int& i, int lane){
    #pragma unroll
    for (int k = 2; k <= 32; k <<= 1){
        #pragma unroll
        for (int j = k >> 1; j > 0; j >>= 1){
            float od = __shfl_xor_sync(FULLM, d, j);
            int   oi = __shfl_xor_sync(FULLM, i, j);
            bool lower = (lane & j) == 0;
            bool asc   = (lane & k) == 0;
            bool osm   = (od < d) || (od == d && oi < i);
            bool take  = (lower == asc) ? osm : !osm;
            if (take){ d = od; i = oi; }
        }
    }
}

// Exact top-16 of NT*32 candidates. sp holds (x,y,z,|p|^2) per point.
// Returns the set of 16 nearest indices distributed on lanes 0..15
// (arbitrary order — callers only max-pool over the set).
template<int NT>
__device__ __forceinline__ int knn16_select(
    const float4* __restrict__ sp,
    float qx, float qy, float qz, int lane,
    float* scand, int* sidxs)
{
    // --- phase 1: per-lane min distance (4 independent chains) -------------
    float m0 = BIGF, m1 = BIGF, m2 = BIGF, m3 = BIGF;
    #pragma unroll
    for (int t = 0; t < NT; t += 4){
        float d0 = qdist(sp[lane + (t  )*32], qx, qy, qz);
        float d1 = qdist(sp[lane + (t+1)*32], qx, qy, qz);
        float d2 = qdist(sp[lane + (t+2)*32], qx, qy, qz);
        float d3 = qdist(sp[lane + (t+3)*32], qx, qy, qz);
        m0 = fminf(m0, d0); m1 = fminf(m1, d1);
        m2 = fminf(m2, d2); m3 = fminf(m3, d3);
    }
    float bd = fminf(fminf(m0, m1), fminf(m2, m3));

    // --- phase 2: threshold = 16th-smallest lane minimum (valid bound) -----
    float thr = __shfl_sync(FULLM, bsort32_val(bd, lane), 15);

    // --- phase 3: recompute + ballot-compact all d <= thr ------------------
    scand[lane] = BIGF; sidxs[lane] = 0x7FFFFFFF;
    __syncwarp();
    unsigned lt = (1u << lane) - 1u;
    int cnt = 0;
    #pragma unroll
    for (int t = 0; t < NT; t++){
        float d = qdist(sp[lane + t*32], qx, qy, qz);
        bool p = (d <= thr);
        unsigned mask = __ballot_sync(FULLM, p);
        if (p){
            int pos = cnt + __popc(mask & lt);
            if (pos < 32){ scand[pos] = d; sidxs[pos] = lane + t*32; }
        }
        cnt += __popc(mask);
    }
    __syncwarp();

    int kidx;
    if (cnt <= 32){
        float d2 = scand[lane]; int i2 = sidxs[lane];
        // value-only sort to find the 16th-smallest distance in the buffer
        float thr16 = __shfl_sync(FULLM, bsort32_val(d2, lane), 15);
        unsigned sel = __ballot_sync(FULLM, d2 <= thr16);
        if (__popc(sel) == 16){
            // no boundary tie: selected lanes ARE the exact top-16 set
            __syncwarp();
            if (d2 <= thr16){
                int pos = __popc(sel & lt);
                sidxs[pos] = i2;
            }
            __syncwarp();
            kidx = sidxs[lane & 15];
        } else {
            // boundary tie on distance: exact lex (d, idx) sort
            bsort32_pair(d2, i2, lane);
            kidx = i2;
        }
    } else {
        // --- rare fallback: progressive argmin with lex exclusion ----------
        float lastD = -BIGF; int lastI = -1; kidx = 0x7FFFFFFF;
        for (int r = 0; r < 16; r++){
            float cbd = BIGF; int cbi = 0x7FFFFFFF;
            #pragma unroll
            for (int t = 0; t < NT; t++){
                int j = lane + t*32;
                float d = qdist(sp[j], qx, qy, qz);
                bool gt = (d > lastD) || (d == lastD && j > lastI);
                if (gt && ((d < cbd) || (d == cbd && j < cbi))){ cbd = d; cbi = j; }
            }
            #pragma unroll
            for (int off = 16; off > 0; off >>= 1){
                float od = __shfl_down_sync(FULLM, cbd, off);
                int   oi = __shfl_down_sync(FULLM, cbi, off);
                if (od < cbd || (od == cbd && oi < cbi)){ cbd = od; cbi = oi; }
            }
            lastD = __shfl_sync(FULLM, cbd, 0);
            lastI = __shfl_sync(FULLM, cbi, 0);
            if (lane == r) kidx = lastI;
        }
    }
    return kidx;
}

// ---------------------------------------------------------------------------
// Kernel A: f = lrelu(LN(lrelu(LN(xyz@W0+b0))@W1+b1))  per point
// ---------------------------------------------------------------------------
__global__ void __launch_bounds__(256) kA(
    const float* __restrict__ pc,
    const float* __restrict__ W0, const float* __restrict__ b0,
    const float* __restrict__ g0, const float* __restrict__ be0,
    const float* __restrict__ W1, const float* __restrict__ b1,
    const float* __restrict__ g1, const float* __restrict__ be1)
{
    int i = blockIdx.x*256 + threadIdx.x;
    int b = i >> 10, n = i & 1023;
    const float* p = pc + (size_t)b*3072;
    float x = p[n], y = p[1024+n], z = p[2048+n];

    float t[16];
    #pragma unroll
    for (int c=0;c<16;c++)
        t[c] = fmaf(x, __ldg(&W0[c]), fmaf(y, __ldg(&W0[16+c]), fmaf(z, __ldg(&W0[32+c]), __ldg(&b0[c]))));
    {
        float m=0.f;
        #pragma unroll
        for (int c=0;c<16;c++) m += t[c];
        m *= (1.f/16.f);
        float v=0.f;
        #pragma unroll
        for (int c=0;c<16;c++){ float dd=t[c]-m; v = fmaf(dd,dd,v); }
        v *= (1.f/16.f);
        float inv = rsqrtf(v + 1e-5f);
        #pragma unroll
        for (int c=0;c<16;c++)
            t[c] = lrelu(fmaf((t[c]-m)*inv, __ldg(&g0[c]), __ldg(&be0[c])));
    }
    float u[16];
    #pragma unroll
    for (int o=0;o<16;o++){
        float a = __ldg(&b1[o]);
        #pragma unroll
        for (int c=0;c<16;c++) a = fmaf(t[c], __ldg(&W1[c*16+o]), a);
        u[o] = a;
    }
    {
        float m=0.f;
        #pragma unroll
        for (int c=0;c<16;c++) m += u[c];
        m *= (1.f/16.f);
        float v=0.f;
        #pragma unroll
        for (int c=0;c<16;c++){ float dd=u[c]-m; v = fmaf(dd,dd,v); }
        v *= (1.f/16.f);
        float inv = rsqrtf(v + 1e-5f);
        #pragma unroll
        for (int c=0;c<16;c++)
            u[c] = lrelu(fmaf((u[c]-m)*inv, __ldg(&g1[c]), __ldg(&be1[c])));
    }
    float4* o4 = reinterpret_cast<float4*>(g_feat + (size_t)i*16);
    o4[0] = make_float4(u[0],u[1],u[2],u[3]);
    o4[1] = make_float4(u[4],u[5],u[6],u[7]);
    o4[2] = make_float4(u[8],u[9],u[10],u[11]);
    o4[3] = make_float4(u[12],u[13],u[14],u[15]);
}

// ---------------------------------------------------------------------------
// Kernel B: pointconv1 (K=16 NN of 512 queries over 1024 pts) + fused squeeze
// Persistent grid of 444 blocks (148 SMs x occ 3). Work = 16384 chunks of 8
// queries (64 chunks/batch); each block takes a contiguous run of 36/37
// chunks -> wave-quantization tail ~0.3%. Contiguous runs span <=2 batches,
// so the sp4 staging happens only 1-2x per block.
// ---------------------------------------------------------------------------
#define KB_BLOCKS 444
#define KB_CHUNKS 16384   // 256 batches * 64 chunks

__global__ void __launch_bounds__(256, 3) kB(
    const float* __restrict__ pc,
    const float* __restrict__ Wp, const float* __restrict__ bp,
    const float* __restrict__ Ws, const float* __restrict__ bsv)
{
    __shared__ __align__(16) float4 sp4[1024];
    __shared__ __align__(16) float  sg[8][16][20];
    __shared__ __align__(16) float  scand[8][32];
    __shared__ __align__(16) int    sidxs[8][32];
    __shared__ __align__(16) float  smx[8][32];

    int tid  = threadIdx.x;
    int lane = tid & 31;
    int w    = tid >> 5;
    int bid  = blockIdx.x;

    // contiguous chunk partition: 16384 = 400*37 + 44*36
    int start, cnt;
    if (bid < 400){ start = bid*37;               cnt = 37; }
    else          { start = 14800 + (bid-400)*36; cnt = 36; }

    // packed per-lane GEMM weights: lane = output channel
    unsigned long long wp[9];
    #pragma unroll
    for (int c=0;c<9;c++)
        wp[c] = pk(__ldg(&Wp[(2*c)*32 + lane]), __ldg(&Wp[(2*c+1)*32 + lane]));
    float wr18 = __ldg(&Wp[18*32 + lane]);
    unsigned long long accp = pk(__ldg(&bp[lane]), 0.f);

    // squeeze weights: lane handles output j = lane&7 over c in [cb, cb+8)
    int jq = lane & 7, cb = (lane >> 3) * 8;
    unsigned long long wsp[4];
    #pragma unroll
    for (int i=0;i<4;i++)
        wsp[i] = pk(__ldg(&Ws[(cb+2*i)*8 + jq]), __ldg(&Ws[(cb+2*i+1)*8 + jq]));
    float bsq = __ldg(&bsv[jq]);

    int curB = -1;
    for (int ci = start; ci < start + cnt; ci++){
        int b    = ci >> 6;
        int m    = ((ci & 63) << 3) + w;              // this warp's query
        if (b != curB){
            __syncthreads();                           // old sp4 fully consumed
            const float* p = pc + (size_t)b*3072;
            for (int n = tid; n < 1024; n += 256){
                float X = p[n], Y = p[1024+n], Z = p[2048+n];
                sp4[n] = make_float4(X, Y, Z, fmaf(X,X, fmaf(Y,Y, Z*Z)));
            }
            __syncthreads();
            curB = b;
        }

        int qi = 2*m;                                  // xyz1[m] == xyz0[2m]
        float4 q = sp4[qi];

        int kidx = knn16_select<32>(sp4, q.x, q.y, q.z, lane,
                                    &scand[w][0], &sidxs[w][0]);

        // --- gather neighbors into per-warp smem g[16][20] ------------------
        __syncwarp();
        if (lane < 16){
            int j = kidx;
            float4 xj = sp4[j];
            float* gr = &sg[w][lane][0];
            gr[0]=xj.x-q.x; gr[1]=xj.y-q.y; gr[2]=xj.z-q.z;
            const float4* fr = reinterpret_cast<const float4*>(g_feat + ((size_t)b*1024 + j)*16);
            float4 f0=fr[0], f1=fr[1], f2v=fr[2], f3=fr[3];
            gr[3]=f0.x;  gr[4]=f0.y;  gr[5]=f0.z;  gr[6]=f0.w;
            gr[7]=f1.x;  gr[8]=f1.y;  gr[9]=f1.z;  gr[10]=f1.w;
            gr[11]=f2v.x; gr[12]=f2v.y; gr[13]=f2v.z; gr[14]=f2v.w;
            gr[15]=f3.x; gr[16]=f3.y; gr[17]=f3.z; gr[18]=f3.w;
        }
        __syncwarp();

        // --- GEMM (lane = output channel) via packed FFMA2 + maxpool -------
        float mx = -BIGF;
        #pragma unroll 4
        for (int k=0;k<16;k++){
            const float* gr = &sg[w][k][0];
            ulonglong2 pA = *reinterpret_cast<const ulonglong2*>(gr);
            ulonglong2 pB = *reinterpret_cast<const ulonglong2*>(gr+4);
            ulonglong2 pC = *reinterpret_cast<const ulonglong2*>(gr+8);
            ulonglong2 pD = *reinterpret_cast<const ulonglong2*>(gr+12);
            unsigned long long pE = *reinterpret_cast<const unsigned long long*>(gr+16);
            float  g18 = gr[18];
            unsigned long long acc = accp;
            acc = ffma2(pA.x, wp[0], acc);
            acc = ffma2(pA.y, wp[1], acc);
            acc = ffma2(pB.x, wp[2], acc);
            acc = ffma2(pB.y, wp[3], acc);
            acc = ffma2(pC.x, wp[4], acc);
            acc = ffma2(pC.y, wp[5], acc);
            acc = ffma2(pD.x, wp[6], acc);
            acc = ffma2(pD.y, wp[7], acc);
            acc = ffma2(pE,   wp[8], acc);
            float2 s = upk(acc);
            float a = fmaf(g18, wr18, s.x + s.y);
            mx = fmaxf(mx, lrelu(a));
        }

        // --- fused squeeze via smem transpose: fs = lrelu(mx @ Ws + bs) -----
        smx[w][lane] = mx;
        __syncwarp();
        const unsigned long long* mp =
            reinterpret_cast<const unsigned long long*>(&smx[w][cb]);
        unsigned long long s2 = pk(0.f, 0.f);
        s2 = ffma2(mp[0], wsp[0], s2);
        s2 = ffma2(mp[1], wsp[1], s2);
        s2 = ffma2(mp[2], wsp[2], s2);
        s2 = ffma2(mp[3], wsp[3], s2);
        float2 sv = upk(s2);
        float s = sv.x + sv.y;
        s += __shfl_down_sync(FULLM, s, 16);
        s += __shfl_down_sync(FULLM, s, 8);
        if (lane < 8)
            g_fs[((size_t)b*512 + m)*8 + jq] = lrelu(s + bsq);
    }
}

// ---------------------------------------------------------------------------
// Kernel C: pointconv2 (128 queries, 512 candidates, 11ch -> 128ch) with
// fused per-chunk column-sum. Persistent grid of 444 blocks; 4096 chunks of
// 8 queries (16 chunks/batch), contiguous runs of 9/10 chunks per block.
// Each chunk's 8-query sum is written to g_psum[b][chunk] (deterministic).
// ---------------------------------------------------------------------------
#define KC_CHUNKS 4096    // 256 batches * 16 chunks

__global__ void __launch_bounds__(256, 3) kC(
    const float* __restrict__ pc,
    const float* __restrict__ Wc, const float* __restrict__ bc)
{
    __shared__ __align__(16) float4 sp4[512];
    __shared__ __align__(16) float  sf[512*8];
    __shared__ __align__(16) float  sg[8][16][12];
    __shared__ __align__(16) float  scand[8][32];
    __shared__ __align__(16) int    sidxs[8][32];
    __shared__ float  sacc[8][128];

    int tid  = threadIdx.x;
    int lane = tid & 31;
    int w    = tid >> 5;
    int bid  = blockIdx.x;

    // contiguous chunk partition: 4096 = 100*10 + 344*9
    int start, cnt;
    if (bid < 100){ start = bid*10;              cnt = 10; }
    else          { start = 1000 + (bid-100)*9;  cnt = 9;  }

    // packed weights for 4 output channels per lane (lane, lane+32, +64, +96)
    unsigned long long wq0[5], wq1[5], wq2[5], wq3[5];
    #pragma unroll
    for (int c=0;c<5;c++){
        wq0[c] = pk(__ldg(&Wc[(2*c)*128 + lane]),      __ldg(&Wc[(2*c+1)*128 + lane]));
        wq1[c] = pk(__ldg(&Wc[(2*c)*128 + lane + 32]), __ldg(&Wc[(2*c+1)*128 + lane + 32]));
        wq2[c] = pk(__ldg(&Wc[(2*c)*128 + lane + 64]), __ldg(&Wc[(2*c+1)*128 + lane + 64]));
        wq3[c] = pk(__ldg(&Wc[(2*c)*128 + lane + 96]), __ldg(&Wc[(2*c+1)*128 + lane + 96]));
    }
    float w10_0 = __ldg(&Wc[10*128 + lane]),      w10_1 = __ldg(&Wc[10*128 + lane + 32]);
    float w10_2 = __ldg(&Wc[10*128 + lane + 64]), w10_3 = __ldg(&Wc[10*128 + lane + 96]);
    unsigned long long bp0 = pk(__ldg(&bc[lane]),     0.f);
    unsigned long long bp1 = pk(__ldg(&bc[lane+32]),  0.f);
    unsigned long long bp2 = pk(__ldg(&bc[lane+64]),  0.f);
    unsigned long long bp3 = pk(__ldg(&bc[lane+96]),  0.f);

    int curB = -1;
    for (int ci = start; ci < start + cnt; ci++){
        int b     = ci >> 4;
        int chunk = ci & 15;
        int m2    = (chunk << 3) + w;                 // this warp's query
        if (b != curB){
            __syncthreads();                           // old sp4/sf consumed
            const float* p = pc + (size_t)b*3072;
            for (int m = tid; m < 512; m += 256){
                float X = p[2*m], Y = p[1024+2*m], Z = p[2048+2*m];
                sp4[m] = make_float4(X, Y, Z, fmaf(X,X, fmaf(Y,Y, Z*Z)));
            }
            const float4* src = reinterpret_cast<const float4*>(g_fs + (size_t)b*4096);
            float4* dst = reinterpret_cast<float4*>(sf);
            for (int t = tid; t < 1024; t += 256) dst[t] = src[t];
            __syncthreads();
            curB = b;
        }

        int qi = 4*m2;                                 // xyz2[m2] == xyz1[4*m2]
        float4 q = sp4[qi];

        int kidx = knn16_select<16>(sp4, q.x, q.y, q.z, lane,
                                    &scand[w][0], &sidxs[w][0]);

        __syncwarp();
        if (lane < 16){
            int j = kidx;
            float4 xj = sp4[j];
            float* gr = &sg[w][lane][0];
            gr[0]=xj.x-q.x; gr[1]=xj.y-q.y; gr[2]=xj.z-q.z;
            const float4* fr = reinterpret_cast<const float4*>(sf + j*8);
            float4 f0=fr[0], f1=fr[1];
            gr[3]=f0.x; gr[4]=f0.y; gr[5]=f0.z; gr[6]=f0.w;
            gr[7]=f1.x; gr[8]=f1.y; gr[9]=f1.z; gr[10]=f1.w;
        }
        __syncwarp();

        float mx0=-BIGF, mx1=-BIGF, mx2=-BIGF, mx3=-BIGF;
        #pragma unroll 4
        for (int k=0;k<16;k++){
            const float* gr = &sg[w][k][0];
            ulonglong2 pA = *reinterpret_cast<const ulonglong2*>(gr);     // g0..g3
            ulonglong2 pB = *reinterpret_cast<const ulonglong2*>(gr+4);   // g4..g7
            float4     v2 = *reinterpret_cast<const float4*>(gr+8);       // g8..g11(pad)
            unsigned long long p4 = pk(v2.x, v2.y);
            float g10 = v2.z;
            unsigned long long a0=bp0, a1=bp1, a2=bp2, a3=bp3;
            a0 = ffma2(pA.x, wq0[0], a0); a1 = ffma2(pA.x, wq1[0], a1);
            a2 = ffma2(pA.x, wq2[0], a2); a3 = ffma2(pA.x, wq3[0], a3);
            a0 = ffma2(pA.y, wq0[1], a0); a1 = ffma2(pA.y, wq1[1], a1);
            a2 = ffma2(pA.y, wq2[1], a2); a3 = ffma2(pA.y, wq3[1], a3);
            a0 = ffma2(pB.x, wq0[2], a0); a1 = ffma2(pB.x, wq1[2], a1);
            a2 = ffma2(pB.x, wq2[2], a2); a3 = ffma2(pB.x, wq3[2], a3);
            a0 = ffma2(pB.y, wq0[3], a0); a1 = ffma2(pB.y, wq1[3], a1);
            a2 = ffma2(pB.y, wq2[3], a2); a3 = ffma2(pB.y, wq3[3], a3);
            a0 = ffma2(p4,   wq0[4], a0); a1 = ffma2(p4,   wq1[4], a1);
            a2 = ffma2(p4,   wq2[4], a2); a3 = ffma2(p4,   wq3[4], a3);
            float2 s0 = upk(a0), s1 = upk(a1), s2 = upk(a2), s3 = upk(a3);
            float r0 = fmaf(g10, w10_0, s0.x + s0.y);
            float r1 = fmaf(g10, w10_1, s1.x + s1.y);
            float r2 = fmaf(g10, w10_2, s2.x + s2.y);
            float r3 = fmaf(g10, w10_3, s3.x + s3.y);
            mx0 = fmaxf(mx0, lrelu(r0));
            mx1 = fmaxf(mx1, lrelu(r1));
            mx2 = fmaxf(mx2, lrelu(r2));
            mx3 = fmaxf(mx3, lrelu(r3));
        }

        // deterministic per-chunk reduction of the 8 queries' vectors
        sacc[w][lane]      = mx0;
        sacc[w][lane + 32] = mx1;
        sacc[w][lane + 64] = mx2;
        sacc[w][lane + 96] = mx3;
        __syncthreads();
        if (tid < 128){
            float s = sacc[0][tid];
            #pragma unroll
            for (int ww=1; ww<8; ww++) s += sacc[ww][tid];
            g_psum[((size_t)b*16 + chunk)*128 + tid] = s;
        }
        __syncthreads();                                // sacc reuse barrier
    }
}

// ---------------------------------------------------------------------------
// Kernel D: out[b] = (sum of 16 chunk psums)/128 @ We + be
// ---------------------------------------------------------------------------
__global__ void __launch_bounds__(256) kD(
    const float* __restrict__ We, const float* __restrict__ be,
    float* __restrict__ out)
{
    __shared__ float sbar[128];
    int b = blockIdx.x, tid = threadIdx.x;
    if (tid < 128){
        const float* ps = g_psum + (size_t)b*16*128 + tid;
        float s = 0.f;
        #pragma unroll
        for (int k=0;k<16;k++) s += ps[k*128];
        sbar[tid] = s * (1.f/128.f);
    }
    __syncthreads();
    float acc = __ldg(&be[tid]);
    #pragma unroll 8
    for (int c=0;c<128;c++) acc = fmaf(sbar[c], __ldg(&We[c*256 + tid]), acc);
    out[(size_t)b*256 + tid] = acc;
}

// ---------------------------------------------------------------------------
extern "C" void kernel_launch(void* const* d_in, const int* in_sizes, int n_in,
                              void* d_out, int out_size)
{
    (void)in_sizes; (void)n_in; (void)out_size;
    const float* pc  = (const float*)d_in[0];
    const float* W0  = (const float*)d_in[1];
    const float* b0  = (const float*)d_in[2];
    const float* g0  = (const float*)d_in[3];
    const float* be0 = (const float*)d_in[4];
    const float* W1  = (const float*)d_in[5];
    const float* b1  = (const float*)d_in[6];
    const float* g1  = (const float*)d_in[7];
    const float* be1 = (const float*)d_in[8];
    const float* Wp  = (const float*)d_in[9];
    const float* bp  = (const float*)d_in[10];
    const float* Ws  = (const float*)d_in[11];
    const float* bsv = (const float*)d_in[12];
    const float* Wc  = (const float*)d_in[13];
    const float* bc  = (const float*)d_in[14];
    const float* We  = (const float*)d_in[15];
    const float* be  = (const float*)d_in[16];
    float* out = (float*)d_out;

    kA<<<1024, 256>>>(pc, W0, b0, g0, be0, W1, b1, g1, be1);
    kB<<<KB_BLOCKS, 256>>>(pc, Wp, bp, Ws, bsv);
    kC<<<KB_BLOCKS, 256>>>(pc, Wc, bc);
    kD<<<256, 256>>>(We, be, out);
}